// round 1
// baseline (speedup 1.0000x reference)
#include <cuda_runtime.h>

#define BB 32
#define TT 2048
#define DD 512
#define D4 128
#define TTILE 128
#define NTILE (TT / TTILE)   // 16

__device__ float g_sumdiff[BB * DD];
__device__ float g_wl;

__global__ void zero_kernel() {
    int i = blockIdx.x * blockDim.x + threadIdx.x;
    if (i < BB * DD) g_sumdiff[i] = 0.0f;
    if (i == 0) g_wl = 0.0f;
}

__device__ __forceinline__ float smooth_l1(float d) {
    float ad = fabsf(d);
    return (ad < 1.0f) ? 0.5f * d * d : ad - 0.5f;
}

__global__ __launch_bounds__(256) void main_kernel(
    const float* __restrict__ preds,
    const float* __restrict__ targets,
    const int* __restrict__ lens)
{
    int b    = blockIdx.x >> 4;      // / NTILE
    int tile = blockIdx.x & (NTILE - 1);
    int len  = lens[b];
    int t0   = tile * TTILE;
    if (t0 >= len) return;           // whole tile masked out
    int tend = min(t0 + TTILE, len);

    int d4   = threadIdx.x & 127;    // which float4 lane of D
    int half = threadIdx.x >> 7;     // two t-rows in flight per block

    const float4* __restrict__ p4 =
        (const float4*)(preds + (size_t)b * TT * DD);
    const float4* __restrict__ q4 =
        (const float4*)(targets + (size_t)b * TT * DD);

    float sdx = 0.f, sdy = 0.f, sdz = 0.f, sdw = 0.f;
    float wl = 0.f;

#pragma unroll 4
    for (int t = t0 + half; t < tend; t += 2) {
        float4 p = p4[(size_t)t * D4 + d4];
        float4 q = q4[(size_t)t * D4 + d4];
        float dx = p.x - q.x;
        float dy = p.y - q.y;
        float dz = p.z - q.z;
        float dw = p.w - q.w;
        sdx += dx; sdy += dy; sdz += dz; sdw += dw;
        wl += smooth_l1(dx) + smooth_l1(dy) + smooth_l1(dz) + smooth_l1(dw);
    }

    // per-(b,d) difference sums — distinct addresses, coalesced REDG
    int base = b * DD + d4 * 4;
    atomicAdd(&g_sumdiff[base + 0], sdx);
    atomicAdd(&g_sumdiff[base + 1], sdy);
    atomicAdd(&g_sumdiff[base + 2], sdz);
    atomicAdd(&g_sumdiff[base + 3], sdw);

    // word-loss: block reduce, one atomic per block
    __shared__ float s_wl[256];
    s_wl[threadIdx.x] = wl;
    __syncthreads();
#pragma unroll
    for (int s = 128; s > 0; s >>= 1) {
        if (threadIdx.x < s) s_wl[threadIdx.x] += s_wl[threadIdx.x + s];
        __syncthreads();
    }
    if (threadIdx.x == 0) atomicAdd(&g_wl, s_wl[0]);
}

__global__ __launch_bounds__(512) void finalize_kernel(
    const int* __restrict__ lens, float* __restrict__ out)
{
    __shared__ float s_len[BB];
    __shared__ float s_sumlen;
    __shared__ float s_red[512];
    int tid = threadIdx.x;

    if (tid < BB) s_len[tid] = (float)lens[tid];
    __syncthreads();
    if (tid == 0) {
        float s = 0.f;
        for (int b = 0; b < BB; b++) s += s_len[b];
        s_sumlen = s;
    }
    __syncthreads();

    float acc = 0.f;
#pragma unroll
    for (int b = 0; b < BB; b++) {
        float m = g_sumdiff[b * DD + tid] / s_len[b];
        acc += smooth_l1(m);
    }
    s_red[tid] = acc;
    __syncthreads();
#pragma unroll
    for (int s = 256; s > 0; s >>= 1) {
        if (tid < s) s_red[tid] += s_red[tid + s];
        __syncthreads();
    }
    if (tid == 0) {
        float sentence = s_red[0] / (float)DD;       // sum_b mean_d
        float word     = g_wl / (s_sumlen * (float)DD);
        out[0] = word + sentence / (float)BB;
    }
}

extern "C" void kernel_launch(void* const* d_in, const int* in_sizes, int n_in,
                              void* d_out, int out_size)
{
    const float* preds   = (const float*)d_in[0];
    const float* targets = (const float*)d_in[1];
    const int*   lens    = (const int*)d_in[2];
    float*       out     = (float*)d_out;

    zero_kernel<<<64, 256>>>();
    main_kernel<<<BB * NTILE, 256>>>(preds, targets, lens);
    finalize_kernel<<<1, 512>>>(lens, out);
}

// round 2
// speedup vs baseline: 1.0572x; 1.0572x over previous
#include <cuda_runtime.h>

#define BB 32
#define TT 2048
#define DD 512
#define D4 128
#define NSLOT 16
#define NBLK (BB * NSLOT)   // 512 blocks

// Scratch: zero-initialized at module load; finalizing block re-zeros after
// consuming, so every invocation (incl. graph replays) sees zeroed scratch.
__device__ float    g_sumdiff[BB * DD];
__device__ float    g_wl;
__device__ unsigned g_count;   // self-wrapping ticket via atomicInc

__device__ __forceinline__ float smooth_l1(float d) {
    float ad = fabsf(d);
    return (ad < 1.0f) ? 0.5f * d * d : ad - 0.5f;
}

__global__ __launch_bounds__(256) void fused_kernel(
    const float* __restrict__ preds,
    const float* __restrict__ targets,
    const int* __restrict__ lens,
    float* __restrict__ out)
{
    const int b    = blockIdx.x >> 4;          // / NSLOT
    const int slot = blockIdx.x & (NSLOT - 1);
    const int len  = lens[b];

    const int d4 = threadIdx.x & 127;          // float4 lane in D
    const int th = threadIdx.x >> 7;           // 2 t-rows in flight per block

    const float4* __restrict__ p4 = (const float4*)(preds   + (size_t)b * TT * DD);
    const float4* __restrict__ q4 = (const float4*)(targets + (size_t)b * TT * DD);

    float sdx = 0.f, sdy = 0.f, sdz = 0.f, sdw = 0.f;
    float wl = 0.f;

    // slot-strided t: 32 parallel t-streams per batch, balanced across slots
#pragma unroll 4
    for (int t = slot * 2 + th; t < len; t += 2 * NSLOT) {
        float4 p = __ldcs(&p4[(size_t)t * D4 + d4]);
        float4 q = __ldcs(&q4[(size_t)t * D4 + d4]);
        float dx = p.x - q.x;
        float dy = p.y - q.y;
        float dz = p.z - q.z;
        float dw = p.w - q.w;
        sdx += dx; sdy += dy; sdz += dz; sdw += dw;
        wl += smooth_l1(dx) + smooth_l1(dy) + smooth_l1(dz) + smooth_l1(dw);
    }

    // per-(b,d) difference sums: distinct-address float REDG into L2
    const int base = b * DD + d4 * 4;
    atomicAdd(&g_sumdiff[base + 0], sdx);
    atomicAdd(&g_sumdiff[base + 1], sdy);
    atomicAdd(&g_sumdiff[base + 2], sdz);
    atomicAdd(&g_sumdiff[base + 3], sdw);

    // word-loss partial: block reduce, one atomic per block
    __shared__ float s_wl[256];
    s_wl[threadIdx.x] = wl;
    __syncthreads();
#pragma unroll
    for (int s = 128; s > 0; s >>= 1) {
        if (threadIdx.x < s) s_wl[threadIdx.x] += s_wl[threadIdx.x + s];
        __syncthreads();
    }

    __shared__ bool s_last;
    if (threadIdx.x == 0) {
        atomicAdd(&g_wl, s_wl[0]);
        __threadfence();                              // release partials
        unsigned old = atomicInc(&g_count, NBLK - 1); // wraps to 0 after 512
        s_last = (old == NBLK - 1);
    }
    __syncthreads();
    if (!s_last) return;

    // ---- last block: finalize ----
    __threadfence();                                  // acquire all partials
    const int tid = threadIdx.x;

    __shared__ float s_len[BB];
    __shared__ float s_sumlen;
    if (tid < BB) s_len[tid] = (float)lens[tid];
    __syncthreads();
    if (tid == 0) {
        float s = 0.f;
#pragma unroll
        for (int b2 = 0; b2 < BB; b2++) s += s_len[b2];
        s_sumlen = s;
    }

    float acc = 0.f;
#pragma unroll
    for (int b2 = 0; b2 < BB; b2++) {
        float inv = 1.0f / s_len[b2];
        float m0 = g_sumdiff[b2 * DD + tid]       * inv;
        float m1 = g_sumdiff[b2 * DD + tid + 256] * inv;
        acc += smooth_l1(m0) + smooth_l1(m1);
        g_sumdiff[b2 * DD + tid]       = 0.f;     // re-zero for next invocation
        g_sumdiff[b2 * DD + tid + 256] = 0.f;
    }

    __shared__ float s_red[256];
    s_red[tid] = acc;
    __syncthreads();
#pragma unroll
    for (int s = 128; s > 0; s >>= 1) {
        if (tid < s) s_red[tid] += s_red[tid + s];
        __syncthreads();
    }

    if (tid == 0) {
        float sentence = s_red[0] / (float)DD;                 // sum_b mean_d
        float word     = g_wl / (s_sumlen * (float)DD);
        out[0] = word + sentence / (float)BB;
        g_wl = 0.f;                                            // re-zero
    }
}

extern "C" void kernel_launch(void* const* d_in, const int* in_sizes, int n_in,
                              void* d_out, int out_size)
{
    const float* preds   = (const float*)d_in[0];
    const float* targets = (const float*)d_in[1];
    const int*   lens    = (const int*)d_in[2];
    float*       out     = (float*)d_out;

    fused_kernel<<<NBLK, 256>>>(preds, targets, lens, out);
}